// round 15
// baseline (speedup 1.0000x reference)
#include <cuda_runtime.h>
#include <math.h>

#define NN 30000
#define EE 480000
#define EA (EE + NN)
#define C 64

// ---------------- scratch (static device globals; no allocation) ------------
__device__ __align__(16) float g_x0[NN * C];
__device__ __align__(16) float g_x1[NN * C];
__device__ __align__(16) float g_xl[NN * C];
__device__ __align__(16) float g_xr[NN * C];
__device__ float g_xl8[NN];
__device__ float g_xr8[NN];
__device__ __align__(16) int g_cw[2 * NN];   // [0:NN) cnt, [NN:2NN) wsum(float); zero-on-entry invariant
__device__ int   g_offs[NN + 1];
__device__ int   g_cursor[NN];
__device__ __align__(16) int2 g_edge[EA];    // .x = src, .y = attr bits
__device__ unsigned long long g_pub[64];     // lookback publications (self-resetting)
__device__ int   g_done;                     // self-resetting
__device__ float g_opart[128];

// ---------------- graph preprocessing ---------------------------------------
__global__ void hist_kernel(const int* __restrict__ dst,
                            const float* __restrict__ w, int e) {
    int i = blockIdx.x * blockDim.x + threadIdx.x;
    if (i >= e) return;
    int d = dst[i];
    atomicAdd(&g_cw[d], 1);
    atomicAdd(((float*)g_cw) + NN + d, w[i]);
}

// Single-kernel decoupled-lookback scan of (cnt[i]+1) -> offs/cursor/self-loop.
__global__ __launch_bounds__(512) void scan_lb(int n, int nb) {
    const unsigned FULL = 0xffffffffu;
    __shared__ int sw[16];
    __shared__ int slook[64];
    __shared__ int sprefix;
    int tid = threadIdx.x, lane = tid & 31, wid = tid >> 5;
    int b = blockIdx.x;
    int i = b * 512 + tid;
    int cnt = (i < n) ? g_cw[i] : 0;
    int v = (i < n) ? (cnt + 1) : 0;
    int inc = v;
    #pragma unroll
    for (int o = 1; o < 32; o <<= 1) {
        int y = __shfl_up_sync(FULL, inc, o);
        if (lane >= o) inc += y;
    }
    if (lane == 31) sw[wid] = inc;
    __syncthreads();
    if (tid < 32) {
        int y = (tid < 16) ? sw[tid] : 0;
        #pragma unroll
        for (int o = 1; o < 16; o <<= 1) {
            int z = __shfl_up_sync(FULL, y, o);
            if (tid >= o) y += z;
        }
        if (tid < 16) sw[tid] = y;
    }
    __syncthreads();
    int block_total = sw[15];
    if (tid == 0)
        atomicExch(&g_pub[b], (1ULL << 32) | (unsigned long long)(unsigned)block_total);
    if (tid < 64) slook[tid] = 0;
    __syncthreads();
    if (tid < b) {
        unsigned long long p;
        do { p = atomicAdd(&g_pub[tid], 0ULL); } while (!(p >> 32));
        slook[tid] = (int)(unsigned)p;
    }
    __syncthreads();
    if (tid == 0) {
        int acc = 0;
        for (int k = 0; k < b; k++) acc += slook[k];
        sprefix = acc;
    }
    __syncthreads();
    int warpoff = (wid > 0) ? sw[wid - 1] : 0;
    if (i < n) {
        int off = sprefix + warpoff + inc - v;
        g_offs[i] = off;
        g_cursor[i] = off;
        float ws = ((const float*)g_cw)[NN + i];
        float la = ws / fmaxf((float)cnt, 1.0f);
        g_edge[off + cnt] = make_int2(i, __float_as_int(la));  // self-loop last
        g_cw[i] = 0;
        ((float*)g_cw)[NN + i] = 0.f;
    }
    if (b == nb - 1 && tid == 0) g_offs[n] = sprefix + block_total;
    __syncthreads();
    if (tid == 0) {
        __threadfence();
        int d = atomicAdd(&g_done, 1);
        if (d == nb - 1) {
            for (int k = 0; k < nb; k++) g_pub[k] = 0ULL;
            g_done = 0;
        }
    }
}

// ---------------- TF32 tensor-core GEMM body ---------------------------------
#define MMA_TF32(D, A, B0, B1) \
    asm volatile("mma.sync.aligned.m16n8k8.row.col.f32.tf32.tf32.f32 " \
        "{%0,%1,%2,%3}, {%4,%5,%6,%7}, {%8,%9}, {%0,%1,%2,%3};" \
        : "+f"(D[0]), "+f"(D[1]), "+f"(D[2]), "+f"(D[3]) \
        : "r"(A[0]), "r"(A[1]), "r"(A[2]), "r"(A[3]), "r"(B0), "r"(B1));

__device__ __forceinline__ unsigned smem_u32(const void* p) {
    return (unsigned)__cvta_generic_to_shared(p);
}
__device__ __forceinline__ void cp_async16(unsigned saddr, const void* gptr) {
    asm volatile("cp.async.cg.shared.global [%0], [%1], 16;"
                 :: "r"(saddr), "l"(gptr));
}

#define XS_STRIDE 68
#define WS_STRIDE 72
#define GEMM_SMEM ((128 * XS_STRIDE + 2 * 64 * WS_STRIDE) * 4)

__device__ __forceinline__ void gemm_body(
    unsigned* smu, int gemm_block,
    const float* __restrict__ x,
    const float* __restrict__ Wl, const float* __restrict__ bl,
    const float* __restrict__ Wr, const float* __restrict__ br,
    float* __restrict__ xl, float* __restrict__ xr, int n)
{
    unsigned* xs = smu;                       // [128][68]
    unsigned* ws = smu + 128 * XS_STRIDE;     // [2][64][72]
    int tid = threadIdx.x;
    int rowbase = gemm_block * 128;

    #pragma unroll 2
    for (int i = tid; i < 128 * 16; i += 256) {
        int r = i >> 4, c4 = (i & 15) << 2;
        int row = rowbase + r;
        unsigned sa = smem_u32(xs + r * XS_STRIDE + c4);
        if (row < n) {
            cp_async16(sa, x + row * 64 + c4);
        } else {
            *(uint4*)(xs + r * XS_STRIDE + c4) = make_uint4(0, 0, 0, 0);
        }
    }
    #pragma unroll 2
    for (int i = tid; i < 64 * 16; i += 256) {
        int r = i >> 4, c4 = (i & 15) << 2;
        cp_async16(smem_u32(ws + r * WS_STRIDE + c4), Wl + r * 64 + c4);
        cp_async16(smem_u32(ws + 64 * WS_STRIDE + r * WS_STRIDE + c4), Wr + r * 64 + c4);
    }
    asm volatile("cp.async.commit_group;");
    asm volatile("cp.async.wait_group 0;");
    __syncthreads();

    int lane = tid & 31, wid = tid >> 5;
    int g = lane >> 2, tig = lane & 3;
    int warpM = wid & 3, half = wid >> 2;
    const unsigned* A = xs + (warpM * 32) * XS_STRIDE;
    const unsigned* B = ws + half * 64 * WS_STRIDE;
    const float* bias = half ? br : bl;

    float d[2][8][4];
    #pragma unroll
    for (int ni = 0; ni < 8; ni++) {
        float2 bv = __ldg((const float2*)bias + ni * 4 + tig);
        d[0][ni][0] = bv.x; d[0][ni][1] = bv.y; d[0][ni][2] = bv.x; d[0][ni][3] = bv.y;
        d[1][ni][0] = bv.x; d[1][ni][1] = bv.y; d[1][ni][2] = bv.x; d[1][ni][3] = bv.y;
    }
    #pragma unroll
    for (int kk = 0; kk < 8; kk++) {
        int k0 = kk * 8;
        unsigned a[2][4];
        #pragma unroll
        for (int m = 0; m < 2; m++) {
            const unsigned* ap = A + (m * 16 + g) * XS_STRIDE + k0 + tig;
            a[m][0] = ap[0];
            a[m][1] = ap[8 * XS_STRIDE];
            a[m][2] = ap[4];
            a[m][3] = ap[8 * XS_STRIDE + 4];
        }
        #pragma unroll
        for (int ni = 0; ni < 8; ni++) {
            unsigned b0 = B[(k0 + tig) * WS_STRIDE + ni * 8 + g];
            unsigned b1 = B[(k0 + tig + 4) * WS_STRIDE + ni * 8 + g];
            MMA_TF32(d[0][ni], a[0], b0, b1);
            MMA_TF32(d[1][ni], a[1], b0, b1);
        }
    }
    float* out = half ? xr : xl;
    #pragma unroll
    for (int m = 0; m < 2; m++) {
        int r0 = rowbase + warpM * 32 + m * 16 + g;
        #pragma unroll
        for (int ni = 0; ni < 8; ni++) {
            int col = ni * 8 + tig * 2;
            if (r0 < n)
                *(float2*)(out + r0 * 64 + col) = make_float2(d[m][ni][0], d[m][ni][1]);
            if (r0 + 8 < n)
                *(float2*)(out + (r0 + 8) * 64 + col) = make_float2(d[m][ni][2], d[m][ni][3]);
        }
    }
}

__global__ __launch_bounds__(256, 2) void gemm_mma_kernel(
    const float* __restrict__ x,
    const float* __restrict__ Wl, const float* __restrict__ bl,
    const float* __restrict__ Wr, const float* __restrict__ br,
    float* __restrict__ xl, float* __restrict__ xr, int n)
{
    extern __shared__ unsigned smu[];
    gemm_body(smu, blockIdx.x, x, Wl, bl, Wr, br, xl, xr, n);
}

// Layer-1 GEMM fused with the CSR edge scatter.
__global__ __launch_bounds__(256, 2) void gemm_scatter_kernel(
    const float* __restrict__ x,
    const float* __restrict__ Wl, const float* __restrict__ bl,
    const float* __restrict__ Wr, const float* __restrict__ br,
    float* __restrict__ xl, float* __restrict__ xr, int n, int gemm_blocks,
    const int* __restrict__ src, const int* __restrict__ dst,
    const float* __restrict__ w, int e, int sblocks)
{
    extern __shared__ unsigned smu[];
    if ((int)blockIdx.x >= gemm_blocks) {
        int sb = blockIdx.x - gemm_blocks;
        int stride = sblocks * 256;
        for (int i = sb * 256 + threadIdx.x; i < e; i += stride) {
            int d = dst[i];
            int p = atomicAdd(&g_cursor[d], 1);
            g_edge[p] = make_int2(src[i], __float_as_int(w[i]));
        }
        return;
    }
    gemm_body(smu, blockIdx.x, x, Wl, bl, Wr, br, xl, xr, n);
}

// -------- fused attention + aggregation: warp/node, 4 edges/iter, ----------
// 2-batch-deep software pipeline (meta ring depth 4, data ring depth 2):
// gathers issued 2 iterations before use -> ~8 edges in flight per warp.
__global__ __launch_bounds__(256, 3) void aggr_kernel(
    const float* __restrict__ xl, const float* __restrict__ xr,
    const float* __restrict__ We, const float* __restrict__ att,
    const float* __restrict__ bo, float* __restrict__ out, int n)
{
    const unsigned FULL = 0xffffffffu;
    int warp = (blockIdx.x * blockDim.x + threadIdx.x) >> 5;
    int lane = threadIdx.x & 31;
    if (warp >= n) return;
    int node = warp;
    int grp = lane >> 3;         // edge slot within the 4-edge batch
    int lid = lane & 7;          // channel group: channels [8*lid, 8*lid+8)
    int base = 2 * lid;
    const float4* xl4 = (const float4*)xl;
    float4 xr0 = ((const float4*)(xr + node * 64))[base];
    float4 xr1 = ((const float4*)(xr + node * 64))[base + 1];
    float4 We0 = __ldg((const float4*)We + base);
    float4 We1 = __ldg((const float4*)We + base + 1);
    float4 at0 = __ldg((const float4*)att + base);
    float4 at1 = __ldg((const float4*)att + base + 1);
    int beg = __ldg(&g_offs[node]), end = __ldg(&g_offs[node + 1]);
    float s = 0.f;
    float a0 = 0.f, a1 = 0.f, a2 = 0.f, a3 = 0.f;
    float a4 = 0.f, a5 = 0.f, a6 = 0.f, a7 = 0.f;

    // prologue: meta for batches 0..3, data for batches 0..1 (clamped to beg)
    int j;
    j = beg + grp;       int2 enA = __ldg(&g_edge[j < end ? j : beg]);
    j = beg + 4 + grp;   int2 enB = __ldg(&g_edge[j < end ? j : beg]);
    j = beg + 8 + grp;   int2 enC = __ldg(&g_edge[j < end ? j : beg]);
    j = beg + 12 + grp;  int2 enD = __ldg(&g_edge[j < end ? j : beg]);
    float4 xA0 = xl4[enA.x * 16 + base];
    float4 xA1 = xl4[enA.x * 16 + base + 1];
    float4 xB0 = xl4[enB.x * 16 + base];
    float4 xB1 = xl4[enB.x * 16 + base + 1];

    for (int j0 = beg; j0 < end; j0 += 4) {
        // issue prefetches first: data(batch+2) via enC, meta(batch+4)
        float4 xN0 = xl4[enC.x * 16 + base];
        float4 xN1 = xl4[enC.x * 16 + base + 1];
        int jn = j0 + 16 + grp;
        int2 enN = __ldg(&g_edge[jn < end ? jn : beg]);

        // compute current batch from (enA, xA)
        float w = __int_as_float(enA.y);
        bool valid = (j0 + grp) < end;
        float e0 = fmaf(w, We0.x, xA0.x + xr0.x);
        float e1 = fmaf(w, We0.y, xA0.y + xr0.y);
        float e2 = fmaf(w, We0.z, xA0.z + xr0.z);
        float e3 = fmaf(w, We0.w, xA0.w + xr0.w);
        float e4 = fmaf(w, We1.x, xA1.x + xr1.x);
        float e5 = fmaf(w, We1.y, xA1.y + xr1.y);
        float e6 = fmaf(w, We1.z, xA1.z + xr1.z);
        float e7 = fmaf(w, We1.w, xA1.w + xr1.w);
        float l0 = fmaxf(e0, 0.2f * e0);
        float l1 = fmaxf(e1, 0.2f * e1);
        float l2 = fmaxf(e2, 0.2f * e2);
        float l3 = fmaxf(e3, 0.2f * e3);
        float l4 = fmaxf(e4, 0.2f * e4);
        float l5 = fmaxf(e5, 0.2f * e5);
        float l6 = fmaxf(e6, 0.2f * e6);
        float l7 = fmaxf(e7, 0.2f * e7);
        float t = l0 * at0.x + l1 * at0.y + l2 * at0.z + l3 * at0.w
                + l4 * at1.x + l5 * at1.y + l6 * at1.z + l7 * at1.w;
        t += __shfl_xor_sync(FULL, t, 4);
        t += __shfl_xor_sync(FULL, t, 2);
        t += __shfl_xor_sync(FULL, t, 1);
        float p = valid ? __expf(t) : 0.f;
        s += p;
        a0 = fmaf(p, xA0.x, a0);
        a1 = fmaf(p, xA0.y, a1);
        a2 = fmaf(p, xA0.z, a2);
        a3 = fmaf(p, xA0.w, a3);
        a4 = fmaf(p, xA1.x, a4);
        a5 = fmaf(p, xA1.y, a5);
        a6 = fmaf(p, xA1.z, a6);
        a7 = fmaf(p, xA1.w, a7);

        // rotate pipeline
        enA = enB; enB = enC; enC = enD; enD = enN;
        xA0 = xB0; xA1 = xB1; xB0 = xN0; xB1 = xN1;
    }
    // merge the four edge-groups' accumulators
    #pragma unroll
    for (int o = 8; o <= 16; o <<= 1) {
        s  += __shfl_xor_sync(FULL, s, o);
        a0 += __shfl_xor_sync(FULL, a0, o);
        a1 += __shfl_xor_sync(FULL, a1, o);
        a2 += __shfl_xor_sync(FULL, a2, o);
        a3 += __shfl_xor_sync(FULL, a3, o);
        a4 += __shfl_xor_sync(FULL, a4, o);
        a5 += __shfl_xor_sync(FULL, a5, o);
        a6 += __shfl_xor_sync(FULL, a6, o);
        a7 += __shfl_xor_sync(FULL, a7, o);
    }
    if (grp == 0) {
        float inv = 1.f / s;
        float4 b0 = __ldg((const float4*)bo + base);
        float4 b1 = __ldg((const float4*)bo + base + 1);
        float4 o0, o1;
        o0.x = fmaf(a0, inv, b0.x);
        o0.y = fmaf(a1, inv, b0.y);
        o0.z = fmaf(a2, inv, b0.z);
        o0.w = fmaf(a3, inv, b0.w);
        o1.x = fmaf(a4, inv, b1.x);
        o1.y = fmaf(a5, inv, b1.y);
        o1.z = fmaf(a6, inv, b1.z);
        o1.w = fmaf(a7, inv, b1.w);
        ((float4*)(out + node * 64))[base] = o0;
        ((float4*)(out + node * 64))[base + 1] = o1;
    }
}

// ---------------- final layer (C -> 1) + mean pool --------------------------
__global__ void gemm8_kernel(const float* __restrict__ x,
                             const float* __restrict__ Wl, const float* __restrict__ bl,
                             const float* __restrict__ Wr, const float* __restrict__ br,
                             int n)
{
    int w = (blockIdx.x * blockDim.x + threadIdx.x) >> 5;
    int lane = threadIdx.x & 31;
    if (w >= n) return;
    float2 xv = ((const float2*)(x + w * 64))[lane];
    float2 wl = __ldg(((const float2*)Wl) + lane);
    float2 wr = __ldg(((const float2*)Wr) + lane);
    float tl = xv.x * wl.x + xv.y * wl.y;
    float tr = xv.x * wr.x + xv.y * wr.y;
    #pragma unroll
    for (int o = 16; o; o >>= 1) {
        tl += __shfl_xor_sync(0xffffffffu, tl, o);
        tr += __shfl_xor_sync(0xffffffffu, tr, o);
    }
    if (lane == 0) {
        g_xl8[w] = tl + __ldg(bl);
        g_xr8[w] = tr + __ldg(br);
    }
}

__global__ __launch_bounds__(256) void aggr8_kernel(
    const float* __restrict__ We8, const float* __restrict__ att8,
    const float* __restrict__ bo8, int n)
{
    int i = blockIdx.x * blockDim.x + threadIdx.x;
    float r = 0.f;
    if (i < n) {
        float wev = __ldg(We8);
        float attv = __ldg(att8);
        float xrv = g_xr8[i];
        int beg = g_offs[i], end = g_offs[i + 1];
        float s = 0.f, acc = 0.f;
        for (int j = beg; j < end; ++j) {
            int2 ev = __ldg(&g_edge[j]);
            float w = __int_as_float(ev.y);
            float xls = g_xl8[ev.x];
            float e = xls + xrv + w * wev;
            float l = fmaxf(e, 0.2f * e);
            float p = __expf(l * attv);
            s += p;
            acc = fmaf(p, xls, acc);
        }
        r = (acc / s + __ldg(bo8)) / (float)n;
    }
    __shared__ float red[256];
    red[threadIdx.x] = r;
    __syncthreads();
    for (int st = 128; st; st >>= 1) {
        if (threadIdx.x < st) red[threadIdx.x] += red[threadIdx.x + st];
        __syncthreads();
    }
    if (threadIdx.x == 0) g_opart[blockIdx.x] = red[0];
}

__global__ void sum_out_kernel(float* __restrict__ out, int nb) {
    int tid = threadIdx.x;
    float v = (tid < nb) ? g_opart[tid] : 0.f;
    __shared__ float red[128];
    red[tid] = v;
    __syncthreads();
    for (int st = 64; st; st >>= 1) {
        if (tid < st) red[tid] += red[tid + st];
        __syncthreads();
    }
    if (tid == 0) out[0] = red[0];
}

// ---------------- host launch ------------------------------------------------
static void* sym(const void* s) { void* p = nullptr; cudaGetSymbolAddress(&p, s); return p; }

extern "C" void kernel_launch(void* const* d_in, const int* in_sizes, int n_in,
                              void* d_out, int out_size)
{
    const float* features = (const float*)d_in[0];
    const int*   e_src    = (const int*)d_in[1];
    const int*   e_dst    = (const int*)d_in[2];
    const float* e_w      = (const float*)d_in[3];
    const float* Wl1 = (const float*)d_in[4];  const float* bl1 = (const float*)d_in[5];
    const float* Wr1 = (const float*)d_in[6];  const float* br1 = (const float*)d_in[7];
    const float* We1 = (const float*)d_in[8];  const float* att1 = (const float*)d_in[9];
    const float* bo1 = (const float*)d_in[10];
    const float* Wlm = (const float*)d_in[11]; const float* blm = (const float*)d_in[12];
    const float* Wrm = (const float*)d_in[13]; const float* brm = (const float*)d_in[14];
    const float* Wem = (const float*)d_in[15]; const float* attm = (const float*)d_in[16];
    const float* bom = (const float*)d_in[17];
    const float* Wl8 = (const float*)d_in[18]; const float* bl8 = (const float*)d_in[19];
    const float* Wr8 = (const float*)d_in[20]; const float* br8 = (const float*)d_in[21];
    const float* We8 = (const float*)d_in[22]; const float* att8 = (const float*)d_in[23];
    const float* bo8 = (const float*)d_in[24];

    int n = in_sizes[0] / C;
    int e = in_sizes[1];
    float* out = (float*)d_out;

    float* x0 = (float*)sym(g_x0);
    float* x1 = (float*)sym(g_x1);
    float* xl = (float*)sym(g_xl);
    float* xr = (float*)sym(g_xr);

    cudaFuncSetAttribute(gemm_mma_kernel,
                         cudaFuncAttributeMaxDynamicSharedMemorySize, GEMM_SMEM);
    cudaFuncSetAttribute(gemm_scatter_kernel,
                         cudaFuncAttributeMaxDynamicSharedMemorySize, GEMM_SMEM);

    int eb = (e + 255) / 256;
    int nb512 = (n + 511) / 512;
    int gemm_blocks = (n + 127) / 128;
    int aggr_blocks = (n * 32 + 255) / 256;
    const int SBLOCKS = 96;

    hist_kernel<<<eb, 256>>>(e_dst, e_w, e);                       // k1
    scan_lb<<<nb512, 512>>>(n, nb512);                             // k2
    gemm_scatter_kernel<<<gemm_blocks + SBLOCKS, 256, GEMM_SMEM>>>(
        features, Wl1, bl1, Wr1, br1, xl, xr, n, gemm_blocks,
        e_src, e_dst, e_w, e, SBLOCKS);                            // k3
    aggr_kernel<<<aggr_blocks, 256>>>(xl, xr, We1, att1, bo1, x0, n);  // k4 <- profiled

    float* cur = x0;
    float* nxt = x1;
    for (int i = 0; i < 6; i++) {
        gemm_mma_kernel<<<gemm_blocks, 256, GEMM_SMEM>>>(cur, Wlm + i * 4096, blm + i * 64,
                                                         Wrm + i * 4096, brm + i * 64, xl, xr, n);
        aggr_kernel<<<aggr_blocks, 256>>>(xl, xr, Wem + i * 64, attm + i * 64,
                                          bom + i * 64, nxt, n);
        float* t = cur; cur = nxt; nxt = t;
    }

    gemm8_kernel<<<(n * 32 + 255) / 256, 256>>>(cur, Wl8, bl8, Wr8, br8, n);
    int ab8 = (n + 255) / 256;
    aggr8_kernel<<<ab8, 256>>>(We8, att8, bo8, n);
    sum_out_kernel<<<1, 128>>>(out, ab8);
}

// round 16
// speedup vs baseline: 1.1900x; 1.1900x over previous
#include <cuda_runtime.h>
#include <math.h>

#define NN 30000
#define EE 480000
#define EA (EE + NN)
#define C 64

// ---------------- scratch (static device globals; no allocation) ------------
__device__ __align__(16) float g_x0[NN * C];
__device__ __align__(16) float g_x1[NN * C];
__device__ __align__(16) float g_xl[NN * C];
__device__ __align__(16) float g_xr[NN * C];
__device__ float g_xl8[NN];
__device__ float g_xr8[NN];
__device__ __align__(16) int g_cw[2 * NN];   // [0:NN) cnt, [NN:2NN) wsum(float); zero-on-entry invariant
__device__ int   g_offs[NN + 1];
__device__ int   g_cursor[NN];
__device__ __align__(16) int2 g_edge[EA];    // .x = src, .y = attr bits
__device__ unsigned long long g_pub[64];     // lookback publications (self-resetting)
__device__ int   g_done;                     // self-resetting
__device__ float g_opart[128];

// ---------------- graph preprocessing ---------------------------------------
__global__ void hist_kernel(const int* __restrict__ dst,
                            const float* __restrict__ w, int e) {
    int i = blockIdx.x * blockDim.x + threadIdx.x;
    if (i >= e) return;
    int d = dst[i];
    atomicAdd(&g_cw[d], 1);
    atomicAdd(((float*)g_cw) + NN + d, w[i]);
}

// Single-kernel decoupled-lookback scan of (cnt[i]+1) -> offs/cursor/self-loop.
__global__ __launch_bounds__(512) void scan_lb(int n, int nb) {
    const unsigned FULL = 0xffffffffu;
    __shared__ int sw[16];
    __shared__ int slook[64];
    __shared__ int sprefix;
    int tid = threadIdx.x, lane = tid & 31, wid = tid >> 5;
    int b = blockIdx.x;
    int i = b * 512 + tid;
    int cnt = (i < n) ? g_cw[i] : 0;
    int v = (i < n) ? (cnt + 1) : 0;
    int inc = v;
    #pragma unroll
    for (int o = 1; o < 32; o <<= 1) {
        int y = __shfl_up_sync(FULL, inc, o);
        if (lane >= o) inc += y;
    }
    if (lane == 31) sw[wid] = inc;
    __syncthreads();
    if (tid < 32) {
        int y = (tid < 16) ? sw[tid] : 0;
        #pragma unroll
        for (int o = 1; o < 16; o <<= 1) {
            int z = __shfl_up_sync(FULL, y, o);
            if (tid >= o) y += z;
        }
        if (tid < 16) sw[tid] = y;
    }
    __syncthreads();
    int block_total = sw[15];
    if (tid == 0)
        atomicExch(&g_pub[b], (1ULL << 32) | (unsigned long long)(unsigned)block_total);
    if (tid < 64) slook[tid] = 0;
    __syncthreads();
    if (tid < b) {
        unsigned long long p;
        do { p = atomicAdd(&g_pub[tid], 0ULL); } while (!(p >> 32));
        slook[tid] = (int)(unsigned)p;
    }
    __syncthreads();
    if (tid == 0) {
        int acc = 0;
        for (int k = 0; k < b; k++) acc += slook[k];
        sprefix = acc;
    }
    __syncthreads();
    int warpoff = (wid > 0) ? sw[wid - 1] : 0;
    if (i < n) {
        int off = sprefix + warpoff + inc - v;
        g_offs[i] = off;
        g_cursor[i] = off;
        float ws = ((const float*)g_cw)[NN + i];
        float la = ws / fmaxf((float)cnt, 1.0f);
        g_edge[off + cnt] = make_int2(i, __float_as_int(la));  // self-loop last
        g_cw[i] = 0;
        ((float*)g_cw)[NN + i] = 0.f;
    }
    if (b == nb - 1 && tid == 0) g_offs[n] = sprefix + block_total;
    __syncthreads();
    if (tid == 0) {
        __threadfence();
        int d = atomicAdd(&g_done, 1);
        if (d == nb - 1) {
            for (int k = 0; k < nb; k++) g_pub[k] = 0ULL;
            g_done = 0;
        }
    }
}

// ---------------- TF32 tensor-core GEMM body ---------------------------------
#define MMA_TF32(D, A, B0, B1) \
    asm volatile("mma.sync.aligned.m16n8k8.row.col.f32.tf32.tf32.f32 " \
        "{%0,%1,%2,%3}, {%4,%5,%6,%7}, {%8,%9}, {%0,%1,%2,%3};" \
        : "+f"(D[0]), "+f"(D[1]), "+f"(D[2]), "+f"(D[3]) \
        : "r"(A[0]), "r"(A[1]), "r"(A[2]), "r"(A[3]), "r"(B0), "r"(B1));

__device__ __forceinline__ unsigned smem_u32(const void* p) {
    return (unsigned)__cvta_generic_to_shared(p);
}
__device__ __forceinline__ void cp_async16(unsigned saddr, const void* gptr) {
    asm volatile("cp.async.cg.shared.global [%0], [%1], 16;"
                 :: "r"(saddr), "l"(gptr));
}

#define XS_STRIDE 68
#define WS_STRIDE 72
#define GEMM_SMEM ((128 * XS_STRIDE + 2 * 64 * WS_STRIDE) * 4)

__device__ __forceinline__ void gemm_body(
    unsigned* smu, int gemm_block,
    const float* __restrict__ x,
    const float* __restrict__ Wl, const float* __restrict__ bl,
    const float* __restrict__ Wr, const float* __restrict__ br,
    float* __restrict__ xl, float* __restrict__ xr, int n)
{
    unsigned* xs = smu;                       // [128][68]
    unsigned* ws = smu + 128 * XS_STRIDE;     // [2][64][72]
    int tid = threadIdx.x;
    int rowbase = gemm_block * 128;

    #pragma unroll 2
    for (int i = tid; i < 128 * 16; i += 256) {
        int r = i >> 4, c4 = (i & 15) << 2;
        int row = rowbase + r;
        unsigned sa = smem_u32(xs + r * XS_STRIDE + c4);
        if (row < n) {
            cp_async16(sa, x + row * 64 + c4);
        } else {
            *(uint4*)(xs + r * XS_STRIDE + c4) = make_uint4(0, 0, 0, 0);
        }
    }
    #pragma unroll 2
    for (int i = tid; i < 64 * 16; i += 256) {
        int r = i >> 4, c4 = (i & 15) << 2;
        cp_async16(smem_u32(ws + r * WS_STRIDE + c4), Wl + r * 64 + c4);
        cp_async16(smem_u32(ws + 64 * WS_STRIDE + r * WS_STRIDE + c4), Wr + r * 64 + c4);
    }
    asm volatile("cp.async.commit_group;");
    asm volatile("cp.async.wait_group 0;");
    __syncthreads();

    int lane = tid & 31, wid = tid >> 5;
    int g = lane >> 2, tig = lane & 3;
    int warpM = wid & 3, half = wid >> 2;
    const unsigned* A = xs + (warpM * 32) * XS_STRIDE;
    const unsigned* B = ws + half * 64 * WS_STRIDE;
    const float* bias = half ? br : bl;

    float d[2][8][4];
    #pragma unroll
    for (int ni = 0; ni < 8; ni++) {
        float2 bv = __ldg((const float2*)bias + ni * 4 + tig);
        d[0][ni][0] = bv.x; d[0][ni][1] = bv.y; d[0][ni][2] = bv.x; d[0][ni][3] = bv.y;
        d[1][ni][0] = bv.x; d[1][ni][1] = bv.y; d[1][ni][2] = bv.x; d[1][ni][3] = bv.y;
    }
    #pragma unroll
    for (int kk = 0; kk < 8; kk++) {
        int k0 = kk * 8;
        unsigned a[2][4];
        #pragma unroll
        for (int m = 0; m < 2; m++) {
            const unsigned* ap = A + (m * 16 + g) * XS_STRIDE + k0 + tig;
            a[m][0] = ap[0];
            a[m][1] = ap[8 * XS_STRIDE];
            a[m][2] = ap[4];
            a[m][3] = ap[8 * XS_STRIDE + 4];
        }
        #pragma unroll
        for (int ni = 0; ni < 8; ni++) {
            unsigned b0 = B[(k0 + tig) * WS_STRIDE + ni * 8 + g];
            unsigned b1 = B[(k0 + tig + 4) * WS_STRIDE + ni * 8 + g];
            MMA_TF32(d[0][ni], a[0], b0, b1);
            MMA_TF32(d[1][ni], a[1], b0, b1);
        }
    }
    float* out = half ? xr : xl;
    #pragma unroll
    for (int m = 0; m < 2; m++) {
        int r0 = rowbase + warpM * 32 + m * 16 + g;
        #pragma unroll
        for (int ni = 0; ni < 8; ni++) {
            int col = ni * 8 + tig * 2;
            if (r0 < n)
                *(float2*)(out + r0 * 64 + col) = make_float2(d[m][ni][0], d[m][ni][1]);
            if (r0 + 8 < n)
                *(float2*)(out + (r0 + 8) * 64 + col) = make_float2(d[m][ni][2], d[m][ni][3]);
        }
    }
}

__global__ __launch_bounds__(256, 2) void gemm_mma_kernel(
    const float* __restrict__ x,
    const float* __restrict__ Wl, const float* __restrict__ bl,
    const float* __restrict__ Wr, const float* __restrict__ br,
    float* __restrict__ xl, float* __restrict__ xr, int n)
{
    extern __shared__ unsigned smu[];
    gemm_body(smu, blockIdx.x, x, Wl, bl, Wr, br, xl, xr, n);
}

// Layer-1 GEMM fused with the CSR edge scatter.
__global__ __launch_bounds__(256, 2) void gemm_scatter_kernel(
    const float* __restrict__ x,
    const float* __restrict__ Wl, const float* __restrict__ bl,
    const float* __restrict__ Wr, const float* __restrict__ br,
    float* __restrict__ xl, float* __restrict__ xr, int n, int gemm_blocks,
    const int* __restrict__ src, const int* __restrict__ dst,
    const float* __restrict__ w, int e, int sblocks)
{
    extern __shared__ unsigned smu[];
    if ((int)blockIdx.x >= gemm_blocks) {
        int sb = blockIdx.x - gemm_blocks;
        int stride = sblocks * 256;
        for (int i = sb * 256 + threadIdx.x; i < e; i += stride) {
            int d = dst[i];
            int p = atomicAdd(&g_cursor[d], 1);
            g_edge[p] = make_int2(src[i], __float_as_int(w[i]));
        }
        return;
    }
    gemm_body(smu, blockIdx.x, x, Wl, bl, Wr, br, xl, xr, n);
}

// -------- fused attention + aggregation: warp/node, 4 edges per iteration ---
// R11 shape (best known). 128-thread blocks: finer scheduling granularity,
// 8 blocks/SM at 64 regs fills the regfile exactly (32 warps/SM).
__global__ __launch_bounds__(128) void aggr_kernel(
    const float* __restrict__ xl, const float* __restrict__ xr,
    const float* __restrict__ We, const float* __restrict__ att,
    const float* __restrict__ bo, float* __restrict__ out, int n)
{
    const unsigned FULL = 0xffffffffu;
    int warp = (blockIdx.x * blockDim.x + threadIdx.x) >> 5;
    int lane = threadIdx.x & 31;
    if (warp >= n) return;
    int node = warp;
    int grp = lane >> 3;         // edge slot within the 4-edge batch
    int lid = lane & 7;          // channel group: channels [8*lid, 8*lid+8)
    const float4* xl4 = (const float4*)xl;
    float4 xr0 = ((const float4*)(xr + node * 64))[2 * lid];
    float4 xr1 = ((const float4*)(xr + node * 64))[2 * lid + 1];
    float4 We0 = __ldg((const float4*)We + 2 * lid);
    float4 We1 = __ldg((const float4*)We + 2 * lid + 1);
    float4 at0 = __ldg((const float4*)att + 2 * lid);
    float4 at1 = __ldg((const float4*)att + 2 * lid + 1);
    int beg = __ldg(&g_offs[node]), end = __ldg(&g_offs[node + 1]);
    float s = 0.f;
    float a0 = 0.f, a1 = 0.f, a2 = 0.f, a3 = 0.f;
    float a4 = 0.f, a5 = 0.f, a6 = 0.f, a7 = 0.f;

    int jp = beg + grp;
    int2 en = __ldg(&g_edge[jp < end ? jp : beg]);
    float4 xn0 = xl4[en.x * 16 + 2 * lid];
    float4 xn1 = xl4[en.x * 16 + 2 * lid + 1];
    for (int j0 = beg; j0 < end; j0 += 4) {
        float4 xa0 = xn0, xa1 = xn1;
        float w = __int_as_float(en.y);
        bool valid = (j0 + grp) < end;
        if (j0 + 4 < end) {
            int j1 = j0 + 4 + grp;
            en = __ldg(&g_edge[j1 < end ? j1 : beg]);
            xn0 = xl4[en.x * 16 + 2 * lid];
            xn1 = xl4[en.x * 16 + 2 * lid + 1];
        }
        float e0 = fmaf(w, We0.x, xa0.x + xr0.x);
        float e1 = fmaf(w, We0.y, xa0.y + xr0.y);
        float e2 = fmaf(w, We0.z, xa0.z + xr0.z);
        float e3 = fmaf(w, We0.w, xa0.w + xr0.w);
        float e4 = fmaf(w, We1.x, xa1.x + xr1.x);
        float e5 = fmaf(w, We1.y, xa1.y + xr1.y);
        float e6 = fmaf(w, We1.z, xa1.z + xr1.z);
        float e7 = fmaf(w, We1.w, xa1.w + xr1.w);
        float l0 = fmaxf(e0, 0.2f * e0);
        float l1 = fmaxf(e1, 0.2f * e1);
        float l2 = fmaxf(e2, 0.2f * e2);
        float l3 = fmaxf(e3, 0.2f * e3);
        float l4 = fmaxf(e4, 0.2f * e4);
        float l5 = fmaxf(e5, 0.2f * e5);
        float l6 = fmaxf(e6, 0.2f * e6);
        float l7 = fmaxf(e7, 0.2f * e7);
        float t = l0 * at0.x + l1 * at0.y + l2 * at0.z + l3 * at0.w
                + l4 * at1.x + l5 * at1.y + l6 * at1.z + l7 * at1.w;
        t += __shfl_xor_sync(FULL, t, 4);
        t += __shfl_xor_sync(FULL, t, 2);
        t += __shfl_xor_sync(FULL, t, 1);
        float p = valid ? __expf(t) : 0.f;
        s += p;
        a0 = fmaf(p, xa0.x, a0);
        a1 = fmaf(p, xa0.y, a1);
        a2 = fmaf(p, xa0.z, a2);
        a3 = fmaf(p, xa0.w, a3);
        a4 = fmaf(p, xa1.x, a4);
        a5 = fmaf(p, xa1.y, a5);
        a6 = fmaf(p, xa1.z, a6);
        a7 = fmaf(p, xa1.w, a7);
    }
    #pragma unroll
    for (int o = 8; o <= 16; o <<= 1) {
        s  += __shfl_xor_sync(FULL, s, o);
        a0 += __shfl_xor_sync(FULL, a0, o);
        a1 += __shfl_xor_sync(FULL, a1, o);
        a2 += __shfl_xor_sync(FULL, a2, o);
        a3 += __shfl_xor_sync(FULL, a3, o);
        a4 += __shfl_xor_sync(FULL, a4, o);
        a5 += __shfl_xor_sync(FULL, a5, o);
        a6 += __shfl_xor_sync(FULL, a6, o);
        a7 += __shfl_xor_sync(FULL, a7, o);
    }
    if (grp == 0) {
        float inv = 1.f / s;
        float4 b0 = __ldg((const float4*)bo + 2 * lid);
        float4 b1 = __ldg((const float4*)bo + 2 * lid + 1);
        float4 o0, o1;
        o0.x = fmaf(a0, inv, b0.x);
        o0.y = fmaf(a1, inv, b0.y);
        o0.z = fmaf(a2, inv, b0.z);
        o0.w = fmaf(a3, inv, b0.w);
        o1.x = fmaf(a4, inv, b1.x);
        o1.y = fmaf(a5, inv, b1.y);
        o1.z = fmaf(a6, inv, b1.z);
        o1.w = fmaf(a7, inv, b1.w);
        ((float4*)(out + node * 64))[2 * lid] = o0;
        ((float4*)(out + node * 64))[2 * lid + 1] = o1;
    }
}

// ---------------- final layer (C -> 1) + mean pool --------------------------
__global__ void gemm8_kernel(const float* __restrict__ x,
                             const float* __restrict__ Wl, const float* __restrict__ bl,
                             const float* __restrict__ Wr, const float* __restrict__ br,
                             int n)
{
    int w = (blockIdx.x * blockDim.x + threadIdx.x) >> 5;
    int lane = threadIdx.x & 31;
    if (w >= n) return;
    float2 xv = ((const float2*)(x + w * 64))[lane];
    float2 wl = __ldg(((const float2*)Wl) + lane);
    float2 wr = __ldg(((const float2*)Wr) + lane);
    float tl = xv.x * wl.x + xv.y * wl.y;
    float tr = xv.x * wr.x + xv.y * wr.y;
    #pragma unroll
    for (int o = 16; o; o >>= 1) {
        tl += __shfl_xor_sync(0xffffffffu, tl, o);
        tr += __shfl_xor_sync(0xffffffffu, tr, o);
    }
    if (lane == 0) {
        g_xl8[w] = tl + __ldg(bl);
        g_xr8[w] = tr + __ldg(br);
    }
}

__global__ __launch_bounds__(256) void aggr8_kernel(
    const float* __restrict__ We8, const float* __restrict__ att8,
    const float* __restrict__ bo8, int n)
{
    int i = blockIdx.x * blockDim.x + threadIdx.x;
    float r = 0.f;
    if (i < n) {
        float wev = __ldg(We8);
        float attv = __ldg(att8);
        float xrv = g_xr8[i];
        int beg = g_offs[i], end = g_offs[i + 1];
        float s = 0.f, acc = 0.f;
        for (int j = beg; j < end; ++j) {
            int2 ev = __ldg(&g_edge[j]);
            float w = __int_as_float(ev.y);
            float xls = g_xl8[ev.x];
            float e = xls + xrv + w * wev;
            float l = fmaxf(e, 0.2f * e);
            float p = __expf(l * attv);
            s += p;
            acc = fmaf(p, xls, acc);
        }
        r = (acc / s + __ldg(bo8)) / (float)n;
    }
    __shared__ float red[256];
    red[threadIdx.x] = r;
    __syncthreads();
    for (int st = 128; st; st >>= 1) {
        if (threadIdx.x < st) red[threadIdx.x] += red[threadIdx.x + st];
        __syncthreads();
    }
    if (threadIdx.x == 0) g_opart[blockIdx.x] = red[0];
}

__global__ void sum_out_kernel(float* __restrict__ out, int nb) {
    int tid = threadIdx.x;
    float v = (tid < nb) ? g_opart[tid] : 0.f;
    __shared__ float red[128];
    red[tid] = v;
    __syncthreads();
    for (int st = 64; st; st >>= 1) {
        if (tid < st) red[tid] += red[tid + st];
        __syncthreads();
    }
    if (tid == 0) out[0] = red[0];
}

// ---------------- host launch ------------------------------------------------
static void* sym(const void* s) { void* p = nullptr; cudaGetSymbolAddress(&p, s); return p; }

extern "C" void kernel_launch(void* const* d_in, const int* in_sizes, int n_in,
                              void* d_out, int out_size)
{
    const float* features = (const float*)d_in[0];
    const int*   e_src    = (const int*)d_in[1];
    const int*   e_dst    = (const int*)d_in[2];
    const float* e_w      = (const float*)d_in[3];
    const float* Wl1 = (const float*)d_in[4];  const float* bl1 = (const float*)d_in[5];
    const float* Wr1 = (const float*)d_in[6];  const float* br1 = (const float*)d_in[7];
    const float* We1 = (const float*)d_in[8];  const float* att1 = (const float*)d_in[9];
    const float* bo1 = (const float*)d_in[10];
    const float* Wlm = (const float*)d_in[11]; const float* blm = (const float*)d_in[12];
    const float* Wrm = (const float*)d_in[13]; const float* brm = (const float*)d_in[14];
    const float* Wem = (const float*)d_in[15]; const float* attm = (const float*)d_in[16];
    const float* bom = (const float*)d_in[17];
    const float* Wl8 = (const float*)d_in[18]; const float* bl8 = (const float*)d_in[19];
    const float* Wr8 = (const float*)d_in[20]; const float* br8 = (const float*)d_in[21];
    const float* We8 = (const float*)d_in[22]; const float* att8 = (const float*)d_in[23];
    const float* bo8 = (const float*)d_in[24];

    int n = in_sizes[0] / C;
    int e = in_sizes[1];
    float* out = (float*)d_out;

    float* x0 = (float*)sym(g_x0);
    float* x1 = (float*)sym(g_x1);
    float* xl = (float*)sym(g_xl);
    float* xr = (float*)sym(g_xr);

    cudaFuncSetAttribute(gemm_mma_kernel,
                         cudaFuncAttributeMaxDynamicSharedMemorySize, GEMM_SMEM);
    cudaFuncSetAttribute(gemm_scatter_kernel,
                         cudaFuncAttributeMaxDynamicSharedMemorySize, GEMM_SMEM);

    int eb = (e + 255) / 256;
    int nb512 = (n + 511) / 512;
    int gemm_blocks = (n + 127) / 128;
    int aggr_blocks = (n * 32 + 127) / 128;
    const int SBLOCKS = 96;

    hist_kernel<<<eb, 256>>>(e_dst, e_w, e);                       // k1
    scan_lb<<<nb512, 512>>>(n, nb512);                             // k2
    gemm_scatter_kernel<<<gemm_blocks + SBLOCKS, 256, GEMM_SMEM>>>(
        features, Wl1, bl1, Wr1, br1, xl, xr, n, gemm_blocks,
        e_src, e_dst, e_w, e, SBLOCKS);                            // k3
    aggr_kernel<<<aggr_blocks, 128>>>(xl, xr, We1, att1, bo1, x0, n);  // k4 <- profiled

    float* cur = x0;
    float* nxt = x1;
    for (int i = 0; i < 6; i++) {
        gemm_mma_kernel<<<gemm_blocks, 256, GEMM_SMEM>>>(cur, Wlm + i * 4096, blm + i * 64,
                                                         Wrm + i * 4096, brm + i * 64, xl, xr, n);
        aggr_kernel<<<aggr_blocks, 128>>>(xl, xr, Wem + i * 64, attm + i * 64,
                                          bom + i * 64, nxt, n);
        float* t = cur; cur = nxt; nxt = t;
    }

    gemm8_kernel<<<(n * 32 + 255) / 256, 256>>>(cur, Wl8, bl8, Wr8, br8, n);
    int ab8 = (n + 255) / 256;
    aggr8_kernel<<<ab8, 256>>>(We8, att8, bo8, n);
    sum_out_kernel<<<1, 128>>>(out, ab8);
}

// round 17
// speedup vs baseline: 1.2212x; 1.0263x over previous
#include <cuda_runtime.h>
#include <math.h>

#define NN 30000
#define EE 480000
#define EA (EE + NN)
#define C 64

// ---------------- scratch (static device globals; no allocation) ------------
__device__ __align__(16) float g_x0[NN * C];
__device__ __align__(16) float g_x1[NN * C];
__device__ __align__(16) float g_xl[NN * C];
__device__ __align__(16) float g_xr[NN * C];
__device__ float g_xl8[NN];
__device__ float g_xr8[NN];
__device__ __align__(16) int g_cw[2 * NN];   // [0:NN) cnt, [NN:2NN) wsum(float); zero-on-entry invariant
__device__ int   g_offs[NN + 1];
__device__ int   g_cursor[NN];
__device__ __align__(16) int2 g_edge[EA];    // .x = src, .y = attr bits
__device__ unsigned long long g_pub[64];     // lookback publications (self-resetting)
__device__ int   g_done;                     // self-resetting
__device__ float g_opart[128];

// ---------------- graph preprocessing ---------------------------------------
__global__ void hist_kernel(const int* __restrict__ dst,
                            const float* __restrict__ w, int e) {
    int i = blockIdx.x * blockDim.x + threadIdx.x;
    if (i >= e) return;
    int d = dst[i];
    atomicAdd(&g_cw[d], 1);
    atomicAdd(((float*)g_cw) + NN + d, w[i]);
}

// Single-kernel decoupled-lookback scan of (cnt[i]+1) -> offs/cursor/self-loop.
__global__ __launch_bounds__(512) void scan_lb(int n, int nb) {
    const unsigned FULL = 0xffffffffu;
    __shared__ int sw[16];
    __shared__ int slook[64];
    __shared__ int sprefix;
    int tid = threadIdx.x, lane = tid & 31, wid = tid >> 5;
    int b = blockIdx.x;
    int i = b * 512 + tid;
    int cnt = (i < n) ? g_cw[i] : 0;
    int v = (i < n) ? (cnt + 1) : 0;
    int inc = v;
    #pragma unroll
    for (int o = 1; o < 32; o <<= 1) {
        int y = __shfl_up_sync(FULL, inc, o);
        if (lane >= o) inc += y;
    }
    if (lane == 31) sw[wid] = inc;
    __syncthreads();
    if (tid < 32) {
        int y = (tid < 16) ? sw[tid] : 0;
        #pragma unroll
        for (int o = 1; o < 16; o <<= 1) {
            int z = __shfl_up_sync(FULL, y, o);
            if (tid >= o) y += z;
        }
        if (tid < 16) sw[tid] = y;
    }
    __syncthreads();
    int block_total = sw[15];
    if (tid == 0)
        atomicExch(&g_pub[b], (1ULL << 32) | (unsigned long long)(unsigned)block_total);
    if (tid < 64) slook[tid] = 0;
    __syncthreads();
    if (tid < b) {
        unsigned long long p;
        do { p = atomicAdd(&g_pub[tid], 0ULL); } while (!(p >> 32));
        slook[tid] = (int)(unsigned)p;
    }
    __syncthreads();
    if (tid == 0) {
        int acc = 0;
        for (int k = 0; k < b; k++) acc += slook[k];
        sprefix = acc;
    }
    __syncthreads();
    int warpoff = (wid > 0) ? sw[wid - 1] : 0;
    if (i < n) {
        int off = sprefix + warpoff + inc - v;
        g_offs[i] = off;
        g_cursor[i] = off;
        float ws = ((const float*)g_cw)[NN + i];
        float la = ws / fmaxf((float)cnt, 1.0f);
        g_edge[off + cnt] = make_int2(i, __float_as_int(la));  // self-loop last
        g_cw[i] = 0;
        ((float*)g_cw)[NN + i] = 0.f;
    }
    if (b == nb - 1 && tid == 0) g_offs[n] = sprefix + block_total;
    __syncthreads();
    if (tid == 0) {
        __threadfence();
        int d = atomicAdd(&g_done, 1);
        if (d == nb - 1) {
            for (int k = 0; k < nb; k++) g_pub[k] = 0ULL;
            g_done = 0;
        }
    }
}

// ---------------- TF32 tensor-core GEMM body ---------------------------------
#define MMA_TF32(D, A, B0, B1) \
    asm volatile("mma.sync.aligned.m16n8k8.row.col.f32.tf32.tf32.f32 " \
        "{%0,%1,%2,%3}, {%4,%5,%6,%7}, {%8,%9}, {%0,%1,%2,%3};" \
        : "+f"(D[0]), "+f"(D[1]), "+f"(D[2]), "+f"(D[3]) \
        : "r"(A[0]), "r"(A[1]), "r"(A[2]), "r"(A[3]), "r"(B0), "r"(B1));

__device__ __forceinline__ unsigned smem_u32(const void* p) {
    return (unsigned)__cvta_generic_to_shared(p);
}
__device__ __forceinline__ void cp_async16(unsigned saddr, const void* gptr) {
    asm volatile("cp.async.cg.shared.global [%0], [%1], 16;"
                 :: "r"(saddr), "l"(gptr));
}

#define XS_STRIDE 68
#define WS_STRIDE 72
#define GEMM_SMEM ((128 * XS_STRIDE + 2 * 64 * WS_STRIDE) * 4)

__device__ __forceinline__ void gemm_body(
    unsigned* smu, int gemm_block,
    const float* __restrict__ x,
    const float* __restrict__ Wl, const float* __restrict__ bl,
    const float* __restrict__ Wr, const float* __restrict__ br,
    float* __restrict__ xl, float* __restrict__ xr, int n)
{
    unsigned* xs = smu;                       // [128][68]
    unsigned* ws = smu + 128 * XS_STRIDE;     // [2][64][72]
    int tid = threadIdx.x;
    int rowbase = gemm_block * 128;

    #pragma unroll 2
    for (int i = tid; i < 128 * 16; i += 256) {
        int r = i >> 4, c4 = (i & 15) << 2;
        int row = rowbase + r;
        unsigned sa = smem_u32(xs + r * XS_STRIDE + c4);
        if (row < n) {
            cp_async16(sa, x + row * 64 + c4);
        } else {
            *(uint4*)(xs + r * XS_STRIDE + c4) = make_uint4(0, 0, 0, 0);
        }
    }
    #pragma unroll 2
    for (int i = tid; i < 64 * 16; i += 256) {
        int r = i >> 4, c4 = (i & 15) << 2;
        cp_async16(smem_u32(ws + r * WS_STRIDE + c4), Wl + r * 64 + c4);
        cp_async16(smem_u32(ws + 64 * WS_STRIDE + r * WS_STRIDE + c4), Wr + r * 64 + c4);
    }
    asm volatile("cp.async.commit_group;");
    asm volatile("cp.async.wait_group 0;");
    __syncthreads();

    int lane = tid & 31, wid = tid >> 5;
    int g = lane >> 2, tig = lane & 3;
    int warpM = wid & 3, half = wid >> 2;
    const unsigned* A = xs + (warpM * 32) * XS_STRIDE;
    const unsigned* B = ws + half * 64 * WS_STRIDE;
    const float* bias = half ? br : bl;

    float d[2][8][4];
    #pragma unroll
    for (int ni = 0; ni < 8; ni++) {
        float2 bv = __ldg((const float2*)bias + ni * 4 + tig);
        d[0][ni][0] = bv.x; d[0][ni][1] = bv.y; d[0][ni][2] = bv.x; d[0][ni][3] = bv.y;
        d[1][ni][0] = bv.x; d[1][ni][1] = bv.y; d[1][ni][2] = bv.x; d[1][ni][3] = bv.y;
    }
    #pragma unroll
    for (int kk = 0; kk < 8; kk++) {
        int k0 = kk * 8;
        unsigned a[2][4];
        #pragma unroll
        for (int m = 0; m < 2; m++) {
            const unsigned* ap = A + (m * 16 + g) * XS_STRIDE + k0 + tig;
            a[m][0] = ap[0];
            a[m][1] = ap[8 * XS_STRIDE];
            a[m][2] = ap[4];
            a[m][3] = ap[8 * XS_STRIDE + 4];
        }
        #pragma unroll
        for (int ni = 0; ni < 8; ni++) {
            unsigned b0 = B[(k0 + tig) * WS_STRIDE + ni * 8 + g];
            unsigned b1 = B[(k0 + tig + 4) * WS_STRIDE + ni * 8 + g];
            MMA_TF32(d[0][ni], a[0], b0, b1);
            MMA_TF32(d[1][ni], a[1], b0, b1);
        }
    }
    float* out = half ? xr : xl;
    #pragma unroll
    for (int m = 0; m < 2; m++) {
        int r0 = rowbase + warpM * 32 + m * 16 + g;
        #pragma unroll
        for (int ni = 0; ni < 8; ni++) {
            int col = ni * 8 + tig * 2;
            if (r0 < n)
                *(float2*)(out + r0 * 64 + col) = make_float2(d[m][ni][0], d[m][ni][1]);
            if (r0 + 8 < n)
                *(float2*)(out + (r0 + 8) * 64 + col) = make_float2(d[m][ni][2], d[m][ni][3]);
        }
    }
}

__global__ __launch_bounds__(256, 2) void gemm_mma_kernel(
    const float* __restrict__ x,
    const float* __restrict__ Wl, const float* __restrict__ bl,
    const float* __restrict__ Wr, const float* __restrict__ br,
    float* __restrict__ xl, float* __restrict__ xr, int n)
{
    extern __shared__ unsigned smu[];
    gemm_body(smu, blockIdx.x, x, Wl, bl, Wr, br, xl, xr, n);
}

// Layer-1 GEMM fused with the CSR edge scatter.
__global__ __launch_bounds__(256, 2) void gemm_scatter_kernel(
    const float* __restrict__ x,
    const float* __restrict__ Wl, const float* __restrict__ bl,
    const float* __restrict__ Wr, const float* __restrict__ br,
    float* __restrict__ xl, float* __restrict__ xr, int n, int gemm_blocks,
    const int* __restrict__ src, const int* __restrict__ dst,
    const float* __restrict__ w, int e, int sblocks)
{
    extern __shared__ unsigned smu[];
    if ((int)blockIdx.x >= gemm_blocks) {
        int sb = blockIdx.x - gemm_blocks;
        int stride = sblocks * 256;
        for (int i = sb * 256 + threadIdx.x; i < e; i += stride) {
            int d = dst[i];
            int p = atomicAdd(&g_cursor[d], 1);
            g_edge[p] = make_int2(src[i], __float_as_int(w[i]));
        }
        return;
    }
    gemm_body(smu, blockIdx.x, x, Wl, bl, Wr, br, xl, xr, n);
}

// -------- fused attention + aggregation: warp/node, 4 edges per iteration ---
// Sector-aligned gathers: lane lid of an 8-lane edge-group loads float4 #lid
// and #(8+lid) of the row -> lanes 0-7 cover bytes 0-127 then 128-255
// contiguously (100% sector utilization vs 50% with the interleaved layout).
// Lane lid owns channels [4*lid,4*lid+4) and [32+4*lid,32+4*lid+4); the
// channel permutation is consistent across xr/We/att/bo and the output.
__global__ __launch_bounds__(128) void aggr_kernel(
    const float* __restrict__ xl, const float* __restrict__ xr,
    const float* __restrict__ We, const float* __restrict__ att,
    const float* __restrict__ bo, float* __restrict__ out, int n)
{
    const unsigned FULL = 0xffffffffu;
    int warp = (blockIdx.x * blockDim.x + threadIdx.x) >> 5;
    int lane = threadIdx.x & 31;
    if (warp >= n) return;
    int node = warp;
    int grp = lane >> 3;         // edge slot within the 4-edge batch
    int lid = lane & 7;          // float4 slot within the row
    const float4* xl4 = (const float4*)xl;
    float4 xr0 = ((const float4*)(xr + node * 64))[lid];
    float4 xr1 = ((const float4*)(xr + node * 64))[8 + lid];
    float4 We0 = __ldg((const float4*)We + lid);
    float4 We1 = __ldg((const float4*)We + 8 + lid);
    float4 at0 = __ldg((const float4*)att + lid);
    float4 at1 = __ldg((const float4*)att + 8 + lid);
    int beg = __ldg(&g_offs[node]), end = __ldg(&g_offs[node + 1]);
    float s = 0.f;
    float a0 = 0.f, a1 = 0.f, a2 = 0.f, a3 = 0.f;
    float a4 = 0.f, a5 = 0.f, a6 = 0.f, a7 = 0.f;

    int jp = beg + grp;
    int2 en = __ldg(&g_edge[jp < end ? jp : beg]);
    float4 xn0 = xl4[en.x * 16 + lid];
    float4 xn1 = xl4[en.x * 16 + 8 + lid];
    for (int j0 = beg; j0 < end; j0 += 4) {
        float4 xa0 = xn0, xa1 = xn1;
        float w = __int_as_float(en.y);
        bool valid = (j0 + grp) < end;
        if (j0 + 4 < end) {
            int j1 = j0 + 4 + grp;
            en = __ldg(&g_edge[j1 < end ? j1 : beg]);
            xn0 = xl4[en.x * 16 + lid];
            xn1 = xl4[en.x * 16 + 8 + lid];
        }
        float e0 = fmaf(w, We0.x, xa0.x + xr0.x);
        float e1 = fmaf(w, We0.y, xa0.y + xr0.y);
        float e2 = fmaf(w, We0.z, xa0.z + xr0.z);
        float e3 = fmaf(w, We0.w, xa0.w + xr0.w);
        float e4 = fmaf(w, We1.x, xa1.x + xr1.x);
        float e5 = fmaf(w, We1.y, xa1.y + xr1.y);
        float e6 = fmaf(w, We1.z, xa1.z + xr1.z);
        float e7 = fmaf(w, We1.w, xa1.w + xr1.w);
        float l0 = fmaxf(e0, 0.2f * e0);
        float l1 = fmaxf(e1, 0.2f * e1);
        float l2 = fmaxf(e2, 0.2f * e2);
        float l3 = fmaxf(e3, 0.2f * e3);
        float l4 = fmaxf(e4, 0.2f * e4);
        float l5 = fmaxf(e5, 0.2f * e5);
        float l6 = fmaxf(e6, 0.2f * e6);
        float l7 = fmaxf(e7, 0.2f * e7);
        float t = l0 * at0.x + l1 * at0.y + l2 * at0.z + l3 * at0.w
                + l4 * at1.x + l5 * at1.y + l6 * at1.z + l7 * at1.w;
        t += __shfl_xor_sync(FULL, t, 4);
        t += __shfl_xor_sync(FULL, t, 2);
        t += __shfl_xor_sync(FULL, t, 1);
        float p = valid ? __expf(t) : 0.f;
        s += p;
        a0 = fmaf(p, xa0.x, a0);
        a1 = fmaf(p, xa0.y, a1);
        a2 = fmaf(p, xa0.z, a2);
        a3 = fmaf(p, xa0.w, a3);
        a4 = fmaf(p, xa1.x, a4);
        a5 = fmaf(p, xa1.y, a5);
        a6 = fmaf(p, xa1.z, a6);
        a7 = fmaf(p, xa1.w, a7);
    }
    #pragma unroll
    for (int o = 8; o <= 16; o <<= 1) {
        s  += __shfl_xor_sync(FULL, s, o);
        a0 += __shfl_xor_sync(FULL, a0, o);
        a1 += __shfl_xor_sync(FULL, a1, o);
        a2 += __shfl_xor_sync(FULL, a2, o);
        a3 += __shfl_xor_sync(FULL, a3, o);
        a4 += __shfl_xor_sync(FULL, a4, o);
        a5 += __shfl_xor_sync(FULL, a5, o);
        a6 += __shfl_xor_sync(FULL, a6, o);
        a7 += __shfl_xor_sync(FULL, a7, o);
    }
    if (grp == 0) {
        float inv = 1.f / s;
        float4 b0 = __ldg((const float4*)bo + lid);
        float4 b1 = __ldg((const float4*)bo + 8 + lid);
        float4 o0, o1;
        o0.x = fmaf(a0, inv, b0.x);
        o0.y = fmaf(a1, inv, b0.y);
        o0.z = fmaf(a2, inv, b0.z);
        o0.w = fmaf(a3, inv, b0.w);
        o1.x = fmaf(a4, inv, b1.x);
        o1.y = fmaf(a5, inv, b1.y);
        o1.z = fmaf(a6, inv, b1.z);
        o1.w = fmaf(a7, inv, b1.w);
        ((float4*)(out + node * 64))[lid] = o0;
        ((float4*)(out + node * 64))[8 + lid] = o1;
    }
}

// ---------------- final layer (C -> 1) + mean pool --------------------------
__global__ void gemm8_kernel(const float* __restrict__ x,
                             const float* __restrict__ Wl, const float* __restrict__ bl,
                             const float* __restrict__ Wr, const float* __restrict__ br,
                             int n)
{
    int w = (blockIdx.x * blockDim.x + threadIdx.x) >> 5;
    int lane = threadIdx.x & 31;
    if (w >= n) return;
    float2 xv = ((const float2*)(x + w * 64))[lane];
    float2 wl = __ldg(((const float2*)Wl) + lane);
    float2 wr = __ldg(((const float2*)Wr) + lane);
    float tl = xv.x * wl.x + xv.y * wl.y;
    float tr = xv.x * wr.x + xv.y * wr.y;
    #pragma unroll
    for (int o = 16; o; o >>= 1) {
        tl += __shfl_xor_sync(0xffffffffu, tl, o);
        tr += __shfl_xor_sync(0xffffffffu, tr, o);
    }
    if (lane == 0) {
        g_xl8[w] = tl + __ldg(bl);
        g_xr8[w] = tr + __ldg(br);
    }
}

__global__ __launch_bounds__(256) void aggr8_kernel(
    const float* __restrict__ We8, const float* __restrict__ att8,
    const float* __restrict__ bo8, int n)
{
    int i = blockIdx.x * blockDim.x + threadIdx.x;
    float r = 0.f;
    if (i < n) {
        float wev = __ldg(We8);
        float attv = __ldg(att8);
        float xrv = g_xr8[i];
        int beg = g_offs[i], end = g_offs[i + 1];
        float s = 0.f, acc = 0.f;
        for (int j = beg; j < end; ++j) {
            int2 ev = __ldg(&g_edge[j]);
            float w = __int_as_float(ev.y);
            float xls = g_xl8[ev.x];
            float e = xls + xrv + w * wev;
            float l = fmaxf(e, 0.2f * e);
            float p = __expf(l * attv);
            s += p;
            acc = fmaf(p, xls, acc);
        }
        r = (acc / s + __ldg(bo8)) / (float)n;
    }
    __shared__ float red[256];
    red[threadIdx.x] = r;
    __syncthreads();
    for (int st = 128; st; st >>= 1) {
        if (threadIdx.x < st) red[threadIdx.x] += red[threadIdx.x + st];
        __syncthreads();
    }
    if (threadIdx.x == 0) g_opart[blockIdx.x] = red[0];
}

__global__ void sum_out_kernel(float* __restrict__ out, int nb) {
    int tid = threadIdx.x;
    float v = (tid < nb) ? g_opart[tid] : 0.f;
    __shared__ float red[128];
    red[tid] = v;
    __syncthreads();
    for (int st = 64; st; st >>= 1) {
        if (tid < st) red[tid] += red[tid + st];
        __syncthreads();
    }
    if (tid == 0) out[0] = red[0];
}

// ---------------- host launch ------------------------------------------------
static void* sym(const void* s) { void* p = nullptr; cudaGetSymbolAddress(&p, s); return p; }

extern "C" void kernel_launch(void* const* d_in, const int* in_sizes, int n_in,
                              void* d_out, int out_size)
{
    const float* features = (const float*)d_in[0];
    const int*   e_src    = (const int*)d_in[1];
    const int*   e_dst    = (const int*)d_in[2];
    const float* e_w      = (const float*)d_in[3];
    const float* Wl1 = (const float*)d_in[4];  const float* bl1 = (const float*)d_in[5];
    const float* Wr1 = (const float*)d_in[6];  const float* br1 = (const float*)d_in[7];
    const float* We1 = (const float*)d_in[8];  const float* att1 = (const float*)d_in[9];
    const float* bo1 = (const float*)d_in[10];
    const float* Wlm = (const float*)d_in[11]; const float* blm = (const float*)d_in[12];
    const float* Wrm = (const float*)d_in[13]; const float* brm = (const float*)d_in[14];
    const float* Wem = (const float*)d_in[15]; const float* attm = (const float*)d_in[16];
    const float* bom = (const float*)d_in[17];
    const float* Wl8 = (const float*)d_in[18]; const float* bl8 = (const float*)d_in[19];
    const float* Wr8 = (const float*)d_in[20]; const float* br8 = (const float*)d_in[21];
    const float* We8 = (const float*)d_in[22]; const float* att8 = (const float*)d_in[23];
    const float* bo8 = (const float*)d_in[24];

    int n = in_sizes[0] / C;
    int e = in_sizes[1];
    float* out = (float*)d_out;

    float* x0 = (float*)sym(g_x0);
    float* x1 = (float*)sym(g_x1);
    float* xl = (float*)sym(g_xl);
    float* xr = (float*)sym(g_xr);

    cudaFuncSetAttribute(gemm_mma_kernel,
                         cudaFuncAttributeMaxDynamicSharedMemorySize, GEMM_SMEM);
    cudaFuncSetAttribute(gemm_scatter_kernel,
                         cudaFuncAttributeMaxDynamicSharedMemorySize, GEMM_SMEM);

    int eb = (e + 255) / 256;
    int nb512 = (n + 511) / 512;
    int gemm_blocks = (n + 127) / 128;
    int aggr_blocks = (n * 32 + 127) / 128;
    const int SBLOCKS = 96;

    hist_kernel<<<eb, 256>>>(e_dst, e_w, e);                       // k1
    scan_lb<<<nb512, 512>>>(n, nb512);                             // k2
    gemm_scatter_kernel<<<gemm_blocks + SBLOCKS, 256, GEMM_SMEM>>>(
        features, Wl1, bl1, Wr1, br1, xl, xr, n, gemm_blocks,
        e_src, e_dst, e_w, e, SBLOCKS);                            // k3
    aggr_kernel<<<aggr_blocks, 128>>>(xl, xr, We1, att1, bo1, x0, n);  // k4 <- profiled

    float* cur = x0;
    float* nxt = x1;
    for (int i = 0; i < 6; i++) {
        gemm_mma_kernel<<<gemm_blocks, 256, GEMM_SMEM>>>(cur, Wlm + i * 4096, blm + i * 64,
                                                         Wrm + i * 4096, brm + i * 64, xl, xr, n);
        aggr_kernel<<<aggr_blocks, 128>>>(xl, xr, Wem + i * 64, attm + i * 64,
                                          bom + i * 64, nxt, n);
        float* t = cur; cur = nxt; nxt = t;
    }

    gemm8_kernel<<<(n * 32 + 255) / 256, 256>>>(cur, Wl8, bl8, Wr8, br8, n);
    int ab8 = (n + 255) / 256;
    aggr8_kernel<<<ab8, 256>>>(We8, att8, bo8, n);
    sum_out_kernel<<<1, 128>>>(out, ab8);
}